// round 11
// baseline (speedup 1.0000x reference)
#include <cuda_runtime.h>
#include <cuda_bf16.h>
#include <math.h>
#include <stdint.h>

// ---------------------------------------------------------------------------
// SpGAT R10: repack moved to main stream (CSR side chain starts at t=0,
// gemm1 has no cross-stream wait); 3-stage agg1/gemm2 pipeline. Kernels
// unchanged from R9.
// ---------------------------------------------------------------------------

#define NN     50000
#define NFEAT  256
#define NHID   64
#define NHEAD  8
#define F1     512
#define NCLASS 40
#define NCPAD  64
#define H2S    64
#define EMAX   1650000
#define ALPHA  0.2f

// ------------------------- device scratch (static) -------------------------
__device__ __nv_bfloat16 g_WcatT[(size_t)F1 * NFEAT];
__device__ __nv_bfloat16 g_H1b  [(size_t)NN * F1];
__device__ __nv_bfloat16 g_ACC1b[(size_t)NN * F1];
__device__ __nv_bfloat16 g_W2T  [(size_t)NCPAD * F1];
__device__ __nv_bfloat16 g_H2b [(size_t)NN * H2S];
__device__ float2 g_esrc[NN * NHEAD];
__device__ float2 g_edst[NN * NHEAD];
__device__ float2 g_e2src[NN];
__device__ float2 g_e2dst[NN];
__device__ int   g_degcnt[2 * NN];
__device__ int   g_rowoff[NN + 1];
__device__ int   g_adj[EMAX];
__device__ int   g_bsum[64];

// ------------------------- weight repack (main stream) ---------------------
__global__ void repack_weights(const float* __restrict__ W1,
                               const float* __restrict__ W2) {
    int stride = gridDim.x * blockDim.x;
    int g = blockIdx.x * blockDim.x + threadIdx.x;
    for (int i = g; i < NHEAD * NFEAT * NHID; i += stride) {
        int h = i / (NFEAT * NHID);
        int r = i % (NFEAT * NHID);
        int k = r / NHID, j = r % NHID;
        g_WcatT[(size_t)(h * NHID + j) * NFEAT + k] = __float2bfloat16(W1[i]);
    }
    for (int i = g; i < NCPAD * F1; i += stride) {
        int n = i / F1, k = i % F1;
        float v = (n < NCLASS) ? W2[(size_t)k * NCLASS + n] : 0.f;
        g_W2T[i] = __float2bfloat16(v);
    }
}

// --------------------------- CSR chain (stream 1) --------------------------
__global__ void hist_kernel(const int* __restrict__ esrc, int E) {
    int e = blockIdx.x * blockDim.x + threadIdx.x;
    if (e < E) atomicAdd(&g_degcnt[esrc[e]], 1);
}

__global__ __launch_bounds__(1024) void scan_block_kernel(int n) {
    int tid = threadIdx.x;
    int gid = blockIdx.x * 1024 + tid;
    int lane = tid & 31, wid = tid >> 5;
    int v = (gid < n) ? g_degcnt[gid] : 0;
    int x = v;
    #pragma unroll
    for (int off = 1; off < 32; off <<= 1) {
        int t = __shfl_up_sync(0xffffffffu, x, off);
        if (lane >= off) x += t;
    }
    __shared__ int wsum[32];
    if (lane == 31) wsum[wid] = x;
    __syncthreads();
    if (wid == 0) {
        int y = wsum[lane];
        #pragma unroll
        for (int off = 1; off < 32; off <<= 1) {
            int t = __shfl_up_sync(0xffffffffu, y, off);
            if (lane >= off) y += t;
        }
        wsum[lane] = y;
    }
    __syncthreads();
    int excl = x - v + (wid ? wsum[wid - 1] : 0);
    if (gid < n) g_rowoff[gid] = excl;
    if (tid == 1023) g_bsum[blockIdx.x] = wsum[31];
}

__global__ __launch_bounds__(1024) void scan_add_kernel(int n, int nb, int E) {
    __shared__ int s[64];
    __shared__ int orig[64];
    int tid = threadIdx.x;
    if (tid < 64) {
        int v = (tid < nb) ? g_bsum[tid] : 0;
        s[tid] = v; orig[tid] = v;
    }
    __syncthreads();
    #pragma unroll
    for (int off = 1; off < 64; off <<= 1) {
        int t = (tid < 64 && tid >= off) ? s[tid - off] : 0;
        __syncthreads();
        if (tid < 64) s[tid] += t;
        __syncthreads();
    }
    int boff = s[blockIdx.x] - orig[blockIdx.x];
    int gid = blockIdx.x * 1024 + tid;
    if (gid < n) g_rowoff[gid] += boff;
    if (blockIdx.x == 0 && tid == 0) g_rowoff[n] = E;
}

__global__ void scatter_kernel(const int* __restrict__ esrc,
                               const int* __restrict__ edst, int E) {
    int e = blockIdx.x * blockDim.x + threadIdx.x;
    if (e < E) {
        int s = esrc[e];
        int pos = g_rowoff[s] + atomicAdd(&g_degcnt[NN + s], 1);
        g_adj[pos] = edst[e];
    }
}

// ------------------------------ mma helpers --------------------------------
#define LDSM4(R0,R1,R2,R3,addr) \
  asm volatile("ldmatrix.sync.aligned.m8n8.x4.shared.b16 {%0,%1,%2,%3}, [%4];" \
    : "=r"(R0),"=r"(R1),"=r"(R2),"=r"(R3) : "r"(addr))

#define MMA16816(D,A,B0,B1) \
  asm volatile("mma.sync.aligned.m16n8k16.row.col.f32.bf16.bf16.f32 " \
    "{%0,%1,%2,%3}, {%4,%5,%6,%7}, {%8,%9}, {%0,%1,%2,%3};" \
    : "+f"(D[0]),"+f"(D[1]),"+f"(D[2]),"+f"(D[3]) \
    : "r"(A[0]),"r"(A[1]),"r"(A[2]),"r"(A[3]),"r"(B0),"r"(B1))

#define CP16(dst, src, n) \
  asm volatile("cp.async.cg.shared.global [%0], [%1], 16, %2;" \
    :: "r"(dst), "l"(src), "r"(n))
#define CP_COMMIT asm volatile("cp.async.commit_group;")

__device__ __forceinline__ uint4 cvt8(float4 a, float4 b) {
    __nv_bfloat162 p0 = __floats2bfloat162_rn(a.x, a.y);
    __nv_bfloat162 p1 = __floats2bfloat162_rn(a.z, a.w);
    __nv_bfloat162 p2 = __floats2bfloat162_rn(b.x, b.y);
    __nv_bfloat162 p3 = __floats2bfloat162_rn(b.z, b.w);
    uint4 u;
    u.x = *(unsigned*)&p0; u.y = *(unsigned*)&p1;
    u.z = *(unsigned*)&p2; u.w = *(unsigned*)&p3;
    return u;
}

// ------------------------- packed f32x2 helpers ----------------------------
__device__ __forceinline__ unsigned long long packf2(float w) {
    unsigned long long r;
    asm("mov.b64 %0, {%1, %1};" : "=l"(r) : "f"(w));
    return r;
}
__device__ __forceinline__ void bf2fma(unsigned long long& acc, unsigned v,
                                       unsigned long long wp) {
    unsigned lo, hi;
    unsigned long long p;
    asm("prmt.b32 %0, %1, 0, 0x1044;" : "=r"(lo) : "r"(v));
    asm("prmt.b32 %0, %1, 0, 0x3244;" : "=r"(hi) : "r"(v));
    asm("mov.b64 %0, {%1, %2};" : "=l"(p) : "r"(lo), "r"(hi));
    asm("fma.rn.f32x2 %0, %1, %2, %0;" : "+l"(acc) : "l"(p), "l"(wp));
}

// ---------------------- GEMM1 (mma + fused attn1 + fused x cvt) ------------
__global__ __launch_bounds__(256, 2) void gemm1_mma(const float* __restrict__ x,
                                                    const float* __restrict__ b1,
                                                    const float* __restrict__ a1,
                                                    int M) {
    const int PAD = 40;
    const int BUFE = 128 * PAD;
    __shared__ __align__(16) __nv_bfloat16 As[2 * BUFE];
    __shared__ __align__(16) __nv_bfloat16 Bs[2 * BUFE];
    int bx = blockIdx.x & 3;
    int by = blockIdx.x >> 2;
    int m0 = by * 128, n0 = bx * 128;
    int tid = threadIdx.x, lane = tid & 31, wid = tid >> 5;
    int wm = (wid & 3) * 32, wn = (wid >> 2) * 64;

    float acc[2][8][4];
    #pragma unroll
    for (int i = 0; i < 2; i++)
        #pragma unroll
        for (int j = 0; j < 8; j++)
            #pragma unroll
            for (int k = 0; k < 4; k++) acc[i][j][k] = 0.f;

    int lr = lane & 7, lb8 = (lane >> 3) & 1, lhi = lane >> 4;
    uint32_t smB = (uint32_t)__cvta_generic_to_shared(Bs);
    uint32_t smA = (uint32_t)__cvta_generic_to_shared(As);
    uint32_t aBase = (uint32_t)((wm + lr + lb8 * 8) * PAD + lhi * 8) * 2;
    uint32_t bBase = (uint32_t)((wn + lr + lhi * 8) * PAD + lb8 * 8) * 2;

    int row0 = tid >> 2, q0 = tid & 3;
    int row1 = row0 + 64, q1 = q0;

    const float4 f4z = make_float4(0.f, 0.f, 0.f, 0.f);
    uint4 ua0, ua1;

    #define LDCVTA(k0) {                                                       \
        int gr0 = m0 + row0, gr1 = m0 + row1;                                  \
        const float* p0 = x + (size_t)(gr0 < M ? gr0 : 0) * NFEAT + (k0) + q0 * 8; \
        const float* p1 = x + (size_t)(gr1 < M ? gr1 : 0) * NFEAT + (k0) + q1 * 8; \
        float4 t0 = __ldg((const float4*)p0), t1 = __ldg((const float4*)p0 + 1); \
        float4 t2 = __ldg((const float4*)p1), t3 = __ldg((const float4*)p1 + 1); \
        if (gr0 >= M) { t0 = f4z; t1 = f4z; }                                  \
        if (gr1 >= M) { t2 = f4z; t3 = f4z; }                                  \
        ua0 = cvt8(t0, t1); ua1 = cvt8(t2, t3);                                \
    }
    #define STA(buf) {                                                         \
        *(uint4*)(&As[(buf) * BUFE + row0 * PAD + q0 * 8]) = ua0;              \
        *(uint4*)(&As[(buf) * BUFE + row1 * PAD + q1 * 8]) = ua1;              \
    }
    #define STAGEB(buf, k0) {                                                  \
        CP16(smB + (buf) * BUFE * 2 + (row0 * PAD + q0 * 8) * 2,               \
             g_WcatT + (size_t)(n0 + row0) * NFEAT + (k0) + q0 * 8, 16);       \
        CP16(smB + (buf) * BUFE * 2 + (row1 * PAD + q1 * 8) * 2,               \
             g_WcatT + (size_t)(n0 + row1) * NFEAT + (k0) + q1 * 8, 16);       \
    }

    LDCVTA(0);
    STAGEB(0, 0); CP_COMMIT;
    for (int kt = 0; kt < 8; kt++) {
        STA(kt & 1);
        if (kt < 7) {
            LDCVTA((kt + 1) * 32);
            STAGEB((kt + 1) & 1, (kt + 1) * 32); CP_COMMIT;
            asm volatile("cp.async.wait_group 1;");
        } else {
            asm volatile("cp.async.wait_group 0;");
        }
        __syncthreads();
        uint32_t aAddr = smA + (kt & 1) * BUFE * 2 + aBase;
        uint32_t bAddr = smB + (kt & 1) * BUFE * 2 + bBase;
        #pragma unroll
        for (int ks = 0; ks < 2; ks++) {
            uint32_t a[2][4], b[4][4];
            #pragma unroll
            for (int mt = 0; mt < 2; mt++)
                LDSM4(a[mt][0], a[mt][1], a[mt][2], a[mt][3],
                      aAddr + mt * 16 * PAD * 2 + ks * 32);
            #pragma unroll
            for (int np = 0; np < 4; np++)
                LDSM4(b[np][0], b[np][1], b[np][2], b[np][3],
                      bAddr + np * 16 * PAD * 2 + ks * 32);
            #pragma unroll
            for (int mt = 0; mt < 2; mt++)
                #pragma unroll
                for (int nt = 0; nt < 8; nt++) {
                    uint32_t b0 = b[nt >> 1][(nt & 1) * 2];
                    uint32_t b1r = b[nt >> 1][(nt & 1) * 2 + 1];
                    MMA16816(acc[mt][nt], a[mt], b0, b1r);
                }
        }
        __syncthreads();
    }

    int gid = lane >> 2, tig = lane & 3;
    int h = (n0 >> 6) + (wid >> 2);
    float ss[4] = {0.f, 0.f, 0.f, 0.f};
    float sd[4] = {0.f, 0.f, 0.f, 0.f};
    #pragma unroll
    for (int mt = 0; mt < 2; mt++) {
        #pragma unroll
        for (int nt = 0; nt < 8; nt++) {
            int j = nt * 8 + tig * 2;
            int c = n0 + wn + j;
            float bb0 = b1[c], bb1 = b1[c + 1];
            float avs0 = a1[h * 128 + j],      avs1 = a1[h * 128 + j + 1];
            float avd0 = a1[h * 128 + 64 + j], avd1 = a1[h * 128 + 64 + j + 1];
            float v0 = acc[mt][nt][0] + bb0, v1 = acc[mt][nt][1] + bb1;
            float v2 = acc[mt][nt][2] + bb0, v3 = acc[mt][nt][3] + bb1;
            ss[mt * 2 + 0] += v0 * avs0 + v1 * avs1;
            sd[mt * 2 + 0] += v0 * avd0 + v1 * avd1;
            ss[mt * 2 + 1] += v2 * avs0 + v3 * avs1;
            sd[mt * 2 + 1] += v2 * avd0 + v3 * avd1;
            int r = m0 + wm + mt * 16 + gid;
            if (r < M) {
                __nv_bfloat162 p = __floats2bfloat162_rn(v0, v1);
                *(unsigned*)(g_H1b + (size_t)r * F1 + c) = *(unsigned*)&p;
            }
            if (r + 8 < M) {
                __nv_bfloat162 p = __floats2bfloat162_rn(v2, v3);
                *(unsigned*)(g_H1b + (size_t)(r + 8) * F1 + c) = *(unsigned*)&p;
            }
        }
    }
    #pragma unroll
    for (int q = 0; q < 4; q++) {
        ss[q] += __shfl_xor_sync(0xffffffffu, ss[q], 1);
        ss[q] += __shfl_xor_sync(0xffffffffu, ss[q], 2);
        sd[q] += __shfl_xor_sync(0xffffffffu, sd[q], 1);
        sd[q] += __shfl_xor_sync(0xffffffffu, sd[q], 2);
    }
    if (tig == 0) {
        #pragma unroll
        for (int q = 0; q < 4; q++) {
            int r = m0 + wm + (q >> 1) * 16 + gid + (q & 1) * 8;
            if (r < M) {
                g_esrc[r * NHEAD + h] = make_float2(__expf(ss[q]), __expf(ALPHA * ss[q]));
                g_edst[r * NHEAD + h] = make_float2(__expf(sd[q]), __expf(ALPHA * sd[q]));
            }
        }
    }
}

// ------------------------------- agg1 --------------------------------------
#define CH1 64
__global__ __launch_bounds__(64) void agg1_kernel(int base) {
    int n = base + blockIdx.x;
    int tid = threadIdx.x;
    int head = tid >> 3;
    __shared__ int   sdst[CH1];
    __shared__ float sw[CH1 * NHEAD];
    __shared__ float2 ses[NHEAD];
    if (tid < NHEAD) ses[tid] = g_esrc[n * NHEAD + tid];
    int start = g_rowoff[n], end = g_rowoff[n + 1];
    unsigned long long accp[4] = {0ull, 0ull, 0ull, 0ull};
    float sumw = 0.f;
    __syncthreads();

    for (int e0 = start; e0 < end; e0 += CH1) {
        int ne = min(CH1, end - e0);
        if (tid < ne) sdst[tid] = g_adj[e0 + tid];
        __syncthreads();
        #pragma unroll
        for (int it = 0; it < 4; it++) {
            int idx = tid + it * 64;
            if (idx < ne * 4) {
                int i = idx >> 2, h2 = (idx & 3) * 2;
                float4 ed = __ldg((const float4*)&g_edst[sdst[i] * NHEAD + h2]);
                float2 es0 = ses[h2], es1 = ses[h2 + 1];
                float p0 = es0.x * ed.x;
                float p1 = es1.x * ed.z;
                sw[i * NHEAD + h2]     = (p0 > 1.f) ? p0 : es0.y * ed.y;
                sw[i * NHEAD + h2 + 1] = (p1 > 1.f) ? p1 : es1.y * ed.w;
            }
        }
        __syncthreads();
        int i = 0;
        for (; i + 4 <= ne; i += 4) {
            float w0 = sw[(i + 0) * NHEAD + head];
            float w1 = sw[(i + 1) * NHEAD + head];
            float w2 = sw[(i + 2) * NHEAD + head];
            float w3 = sw[(i + 3) * NHEAD + head];
            uint4 p0 = __ldg((const uint4*)(g_H1b + (size_t)sdst[i + 0] * F1 + tid * 8));
            uint4 p1 = __ldg((const uint4*)(g_H1b + (size_t)sdst[i + 1] * F1 + tid * 8));
            uint4 p2 = __ldg((const uint4*)(g_H1b + (size_t)sdst[i + 2] * F1 + tid * 8));
            uint4 p3 = __ldg((const uint4*)(g_H1b + (size_t)sdst[i + 3] * F1 + tid * 8));
            sumw += (w0 + w1) + (w2 + w3);
            unsigned long long wp0 = packf2(w0), wp1 = packf2(w1);
            unsigned long long wp2 = packf2(w2), wp3 = packf2(w3);
            bf2fma(accp[0], p0.x, wp0); bf2fma(accp[1], p0.y, wp0);
            bf2fma(accp[2], p0.z, wp0); bf2fma(accp[3], p0.w, wp0);
            bf2fma(accp[0], p1.x, wp1); bf2fma(accp[1], p1.y, wp1);
            bf2fma(accp[2], p1.z, wp1); bf2fma(accp[3], p1.w, wp1);
            bf2fma(accp[0], p2.x, wp2); bf2fma(accp[1], p2.y, wp2);
            bf2fma(accp[2], p2.z, wp2); bf2fma(accp[3], p2.w, wp2);
            bf2fma(accp[0], p3.x, wp3); bf2fma(accp[1], p3.y, wp3);
            bf2fma(accp[2], p3.z, wp3); bf2fma(accp[3], p3.w, wp3);
        }
        for (; i < ne; i++) {
            float w = sw[i * NHEAD + head];
            sumw += w;
            uint4 p = __ldg((const uint4*)(g_H1b + (size_t)sdst[i] * F1 + tid * 8));
            unsigned long long wp = packf2(w);
            bf2fma(accp[0], p.x, wp); bf2fma(accp[1], p.y, wp);
            bf2fma(accp[2], p.z, wp); bf2fma(accp[3], p.w, wp);
        }
        __syncthreads();
    }
    float inv = 1.0f / sumw;
    float acc[8];
    #pragma unroll
    for (int k = 0; k < 4; k++) {
        float lo, hi;
        asm("mov.b64 {%0, %1}, %2;" : "=f"(lo), "=f"(hi) : "l"(accp[k]));
        acc[2 * k] = lo; acc[2 * k + 1] = hi;
    }
    #pragma unroll
    for (int k = 0; k < 8; k++) {
        float v = acc[k] * inv;
        acc[k] = v > 0.f ? v : (__expf(v) - 1.f);
    }
    __nv_bfloat162 q0 = __floats2bfloat162_rn(acc[0], acc[1]);
    __nv_bfloat162 q1 = __floats2bfloat162_rn(acc[2], acc[3]);
    __nv_bfloat162 q2 = __floats2bfloat162_rn(acc[4], acc[5]);
    __nv_bfloat162 q3 = __floats2bfloat162_rn(acc[6], acc[7]);
    uint4 u;
    u.x = *(unsigned*)&q0; u.y = *(unsigned*)&q1;
    u.z = *(unsigned*)&q2; u.w = *(unsigned*)&q3;
    *(uint4*)(g_ACC1b + (size_t)n * F1 + tid * 8) = u;
}

// ---------------------- GEMM2 (mma + fused attn2) --------------------------
__global__ __launch_bounds__(256, 2) void gemm2_mma(const float* __restrict__ b2,
                                                    const float* __restrict__ a2,
                                                    int mbase, int M) {
    const int PAD = 40;
    __shared__ __align__(16) __nv_bfloat16 As[128 * PAD];
    __shared__ __align__(16) __nv_bfloat16 Bs[64 * PAD];
    int m0 = mbase + blockIdx.x * 128;
    int tid = threadIdx.x, lane = tid & 31, wid = tid >> 5;
    int wm = wid * 16;

    float acc[5][4];
    #pragma unroll
    for (int j = 0; j < 5; j++)
        #pragma unroll
        for (int k = 0; k < 4; k++) acc[j][k] = 0.f;

    int lr = lane & 7, lb8 = (lane >> 3) & 1, lhi = lane >> 4;
    uint32_t smA = (uint32_t)__cvta_generic_to_shared(As);
    uint32_t smB = (uint32_t)__cvta_generic_to_shared(Bs);
    uint32_t aAddr = smA + (uint32_t)((wm + lr + lb8 * 8) * PAD + lhi * 8) * 2;
    uint32_t bAddr = smB + (uint32_t)((lr + lhi * 8) * PAD + lb8 * 8) * 2;

    for (int k0 = 0; k0 < F1; k0 += 32) {
        #pragma unroll
        for (int it = 0; it < 2; it++) {
            int idx = tid + it * 256;
            int row = idx >> 2, q = idx & 3;
            int gr = m0 + row;
            uint4 v = make_uint4(0, 0, 0, 0);
            if (gr < M)
                v = *(const uint4*)(g_ACC1b + (size_t)gr * F1 + k0 + q * 8);
            *(uint4*)(&As[row * PAD + q * 8]) = v;
        }
        {
            int row = tid >> 2, q = tid & 3;
            uint4 w = *(const uint4*)(g_W2T + (size_t)row * F1 + k0 + q * 8);
            *(uint4*)(&Bs[row * PAD + q * 8]) = w;
        }
        __syncthreads();
        #pragma unroll
        for (int ks = 0; ks < 2; ks++) {
            uint32_t a[4], b[3][4];
            LDSM4(a[0], a[1], a[2], a[3], aAddr + ks * 32);
            #pragma unroll
            for (int np = 0; np < 3; np++)
                LDSM4(b[np][0], b[np][1], b[np][2], b[np][3],
                      bAddr + np * 16 * PAD * 2 + ks * 32);
            #pragma unroll
            for (int nt = 0; nt < 5; nt++) {
                uint32_t b0 = b[nt >> 1][(nt & 1) * 2];
                uint32_t b1r = b[nt >> 1][(nt & 1) * 2 + 1];
                MMA16816(acc[nt], a, b0, b1r);
            }
        }
        __syncthreads();
    }

    int gid = lane >> 2, tig = lane & 3;
    float ss[2] = {0.f, 0.f}, sd[2] = {0.f, 0.f};
    int r0 = m0 + wm + gid;
    #pragma unroll
    for (int nt = 0; nt < 5; nt++) {
        int c = nt * 8 + tig * 2;
        float bb0 = b2[c], bb1 = b2[c + 1];
        float as0 = a2[c], as1 = a2[c + 1];
        float ad0 = a2[NCLASS + c], ad1 = a2[NCLASS + c + 1];
        float v0 = acc[nt][0] + bb0, v1 = acc[nt][1] + bb1;
        float v2 = acc[nt][2] + bb0, v3 = acc[nt][3] + bb1;
        ss[0] += v0 * as0 + v1 * as1; sd[0] += v0 * ad0 + v1 * ad1;
        ss[1] += v2 * as0 + v3 * as1; sd[1] += v2 * ad0 + v3 * ad1;
        if (r0 < M) {
            __nv_bfloat162 p = __floats2bfloat162_rn(v0, v1);
            *(unsigned*)(g_H2b + (size_t)r0 * H2S + c) = *(unsigned*)&p;
        }
        if (r0 + 8 < M) {
            __nv_bfloat162 p = __floats2bfloat162_rn(v2, v3);
            *(unsigned*)(g_H2b + (size_t)(r0 + 8) * H2S + c) = *(unsigned*)&p;
        }
    }
    #pragma unroll
    for (int q = 0; q < 2; q++) {
        ss[q] += __shfl_xor_sync(0xffffffffu, ss[q], 1);
        ss[q] += __shfl_xor_sync(0xffffffffu, ss[q], 2);
        sd[q] += __shfl_xor_sync(0xffffffffu, sd[q], 1);
        sd[q] += __shfl_xor_sync(0xffffffffu, sd[q], 2);
    }
    if (tig == 0) {
        #pragma unroll
        for (int q = 0; q < 2; q++) {
            int r = r0 + q * 8;
            if (r < M) {
                g_e2src[r] = make_float2(__expf(ss[q]), __expf(ALPHA * ss[q]));
                g_e2dst[r] = make_float2(__expf(sd[q]), __expf(ALPHA * sd[q]));
            }
        }
    }
}

// --------------------------- agg2 + log_softmax ----------------------------
#define CH2 64
__global__ __launch_bounds__(64) void agg2_kernel(float* __restrict__ out) {
    int n = blockIdx.x;
    int tid = threadIdx.x;
    int g = tid / 20, l = tid % 20;
    __shared__ int   sdst[CH2];
    __shared__ float sw[CH2];
    __shared__ unsigned long long pacc[3][20];
    __shared__ float psum[3];
    float2 es = g_e2src[n];
    int start = g_rowoff[n], end = g_rowoff[n + 1];
    unsigned long long accp = 0ull;
    float sumw = 0.f;

    for (int e0 = start; e0 < end; e0 += CH2) {
        int ne = min(CH2, end - e0);
        if (tid < ne) {
            int d = g_adj[e0 + tid];
            sdst[tid] = d;
            float2 ed = __ldg(&g_e2dst[d]);
            float p1 = es.x * ed.x;
            sw[tid] = (p1 > 1.f) ? p1 : es.y * ed.y;
        }
        __syncthreads();
        if (g < 3) {
            int i = g;
            for (; i + 3 < ne; i += 6) {
                float w0 = sw[i], w1 = sw[i + 3];
                sumw += w0 + w1;
                unsigned v0 = *(const unsigned*)(g_H2b + (size_t)sdst[i] * H2S + 2 * l);
                unsigned v1 = *(const unsigned*)(g_H2b + (size_t)sdst[i + 3] * H2S + 2 * l);
                bf2fma(accp, v0, packf2(w0));
                bf2fma(accp, v1, packf2(w1));
            }
            if (i < ne) {
                float w = sw[i];
                sumw += w;
                unsigned v = *(const unsigned*)(g_H2b + (size_t)sdst[i] * H2S + 2 * l);
                bf2fma(accp, v, packf2(w));
            }
        }
        __syncthreads();
    }
    if (g < 3) {
        pacc[g][l] = accp;
        if (l == 0) psum[g] = sumw;
    }
    __syncthreads();

    __shared__ float red[64];
    if (tid < 20) {
        float tot = psum[0] + psum[1] + psum[2];
        float a0, a1, b0, b1, c0, c1;
        asm("mov.b64 {%0, %1}, %2;" : "=f"(a0), "=f"(a1) : "l"(pacc[0][tid]));
        asm("mov.b64 {%0, %1}, %2;" : "=f"(b0), "=f"(b1) : "l"(pacc[1][tid]));
        asm("mov.b64 {%0, %1}, %2;" : "=f"(c0), "=f"(c1) : "l"(pacc[2][tid]));
        float inv = 1.0f / tot;
        red[2 * tid]     = (a0 + b0 + c0) * inv;
        red[2 * tid + 1] = (a1 + b1 + c1) * inv;
    } else if (tid >= 40) {
        red[tid] = -1e30f;
    }
    __syncthreads();
    float v = red[tid];
    #pragma unroll
    for (int s = 32; s; s >>= 1) {
        if (tid < s) red[tid] = fmaxf(red[tid], red[tid + s]);
        __syncthreads();
    }
    float mx = red[0];
    __syncthreads();
    red[tid] = (tid < NCLASS) ? __expf(v - mx) : 0.f;
    __syncthreads();
    #pragma unroll
    for (int s = 32; s; s >>= 1) {
        if (tid < s) red[tid] += red[tid + s];
        __syncthreads();
    }
    float lse = logf(red[0]) + mx;
    if (tid < NCLASS) out[(size_t)n * NCLASS + tid] = v - lse;
}

// ------------------------------- launcher ----------------------------------
extern "C" void kernel_launch(void* const* d_in, const int* in_sizes, int n_in,
                              void* d_out, int out_size) {
    const float* x  = (const float*)d_in[0];
    const int*   ed = (const int*)  d_in[1];
    const float* W1 = (const float*)d_in[2];
    const float* b1 = (const float*)d_in[3];
    const float* a1 = (const float*)d_in[4];
    const float* W2 = (const float*)d_in[5];
    const float* b2 = (const float*)d_in[6];
    const float* a2 = (const float*)d_in[7];
    float* out = (float*)d_out;

    int N = in_sizes[0] / NFEAT;
    int E = in_sizes[1] / 2;
    const int* esrc = ed;
    const int* edst = ed + E;
    int NB = (N + 1023) / 1024;

    static cudaStream_t s1 = nullptr;
    static cudaEvent_t ev0 = nullptr, ev1 = nullptr;
    static cudaEvent_t evA0 = nullptr, evA1 = nullptr, evG = nullptr;
    static void* p_degcnt = nullptr;
    if (s1 == nullptr) {
        cudaStreamCreateWithFlags(&s1, cudaStreamNonBlocking);
        cudaEventCreateWithFlags(&ev0, cudaEventDisableTiming);
        cudaEventCreateWithFlags(&ev1, cudaEventDisableTiming);
        cudaEventCreateWithFlags(&evA0, cudaEventDisableTiming);
        cudaEventCreateWithFlags(&evA1, cudaEventDisableTiming);
        cudaEventCreateWithFlags(&evG, cudaEventDisableTiming);
        cudaGetSymbolAddress(&p_degcnt, g_degcnt);
    }

    cudaEventRecord(ev0, 0);
    cudaStreamWaitEvent(s1, ev0, 0);

    // CSR side chain starts immediately on s1 (no repack in front)
    cudaMemsetAsync(p_degcnt, 0, 2 * N * sizeof(int), s1);
    hist_kernel<<<(E + 255) / 256, 256, 0, s1>>>(esrc, E);
    scan_block_kernel<<<NB, 1024, 0, s1>>>(N);
    scan_add_kernel<<<NB, 1024, 0, s1>>>(N, NB, E);
    scatter_kernel<<<(E + 255) / 256, 256, 0, s1>>>(esrc, edst, E);
    cudaEventRecord(ev1, s1);

    // main: repack (gemm1's only dependency) then gemm1 — same stream, no wait
    repack_weights<<<256, 256>>>(W1, W2);
    gemm1_mma<<<((N + 127) / 128) * (F1 / 128), 256>>>(x, b1, a1, N);

    // 3-stage agg1 / gemm2 pipeline
    int NA1 = 19968;                 // 156 * 128
    int NA2 = 39936;                 // 312 * 128
    if (NA2 > N) { NA1 = (N / 3 / 128) * 128; NA2 = 2 * NA1; }

    cudaStreamWaitEvent(0, ev1, 0);
    agg1_kernel<<<NA1, 64>>>(0);
    cudaEventRecord(evA0, 0);
    agg1_kernel<<<NA2 - NA1, 64>>>(NA1);
    cudaEventRecord(evA1, 0);
    agg1_kernel<<<N - NA2, 64>>>(NA2);

    cudaStreamWaitEvent(s1, evA0, 0);
    gemm2_mma<<<NA1 / 128, 256, 0, s1>>>(b2, a2, 0, N);
    cudaStreamWaitEvent(s1, evA1, 0);
    gemm2_mma<<<(NA2 - NA1) / 128, 256, 0, s1>>>(b2, a2, NA1, N);
    cudaEventRecord(evG, s1);

    gemm2_mma<<<(N - NA2 + 127) / 128, 256>>>(b2, a2, NA2, N);
    cudaStreamWaitEvent(0, evG, 0);
    agg2_kernel<<<N, 64>>>(out);
}

// round 12
// speedup vs baseline: 1.0475x; 1.0475x over previous
#include <cuda_runtime.h>
#include <cuda_bf16.h>
#include <math.h>
#include <stdint.h>

// ---------------------------------------------------------------------------
// SpGAT R11: R9 schedule (352us baseline) + atomic-free scatter (hist stores
// per-edge rank from its atomicAdd return; scatter is a pure streaming pass).
// ---------------------------------------------------------------------------

#define NN     50000
#define NFEAT  256
#define NHID   64
#define NHEAD  8
#define F1     512
#define NCLASS 40
#define NCPAD  64
#define H2S    64
#define EMAX   1650000
#define ALPHA  0.2f

// ------------------------- device scratch (static) -------------------------
__device__ __nv_bfloat16 g_WcatT[(size_t)F1 * NFEAT];
__device__ __nv_bfloat16 g_H1b  [(size_t)NN * F1];
__device__ __nv_bfloat16 g_ACC1b[(size_t)NN * F1];
__device__ __nv_bfloat16 g_W2T  [(size_t)NCPAD * F1];
__device__ __nv_bfloat16 g_H2b [(size_t)NN * H2S];
__device__ float2 g_esrc[NN * NHEAD];
__device__ float2 g_edst[NN * NHEAD];
__device__ float2 g_e2src[NN];
__device__ float2 g_e2dst[NN];
__device__ int   g_deg[NN];
__device__ int   g_rank[EMAX];
__device__ int   g_rowoff[NN + 1];
__device__ int   g_adj[EMAX];
__device__ int   g_bsum[64];

// --------------------------- weight repack (stream 1) ----------------------
__global__ void repack_weights(const float* __restrict__ W1,
                               const float* __restrict__ W2) {
    int stride = gridDim.x * blockDim.x;
    int g = blockIdx.x * blockDim.x + threadIdx.x;
    for (int i = g; i < NHEAD * NFEAT * NHID; i += stride) {
        int h = i / (NFEAT * NHID);
        int r = i % (NFEAT * NHID);
        int k = r / NHID, j = r % NHID;
        g_WcatT[(size_t)(h * NHID + j) * NFEAT + k] = __float2bfloat16(W1[i]);
    }
    for (int i = g; i < NCPAD * F1; i += stride) {
        int n = i / F1, k = i % F1;
        float v = (n < NCLASS) ? W2[(size_t)k * NCLASS + n] : 0.f;
        g_W2T[i] = __float2bfloat16(v);
    }
}

// --------------------------- CSR chain (stream 1) --------------------------
// hist also captures each edge's rank within its source row (atomicAdd return)
__global__ void hist_kernel(const int* __restrict__ esrc, int E) {
    int e = blockIdx.x * blockDim.x + threadIdx.x;
    if (e < E) g_rank[e] = atomicAdd(&g_deg[esrc[e]], 1);
}

__global__ __launch_bounds__(1024) void scan_block_kernel(int n) {
    int tid = threadIdx.x;
    int gid = blockIdx.x * 1024 + tid;
    int lane = tid & 31, wid = tid >> 5;
    int v = (gid < n) ? g_deg[gid] : 0;
    int x = v;
    #pragma unroll
    for (int off = 1; off < 32; off <<= 1) {
        int t = __shfl_up_sync(0xffffffffu, x, off);
        if (lane >= off) x += t;
    }
    __shared__ int wsum[32];
    if (lane == 31) wsum[wid] = x;
    __syncthreads();
    if (wid == 0) {
        int y = wsum[lane];
        #pragma unroll
        for (int off = 1; off < 32; off <<= 1) {
            int t = __shfl_up_sync(0xffffffffu, y, off);
            if (lane >= off) y += t;
        }
        wsum[lane] = y;
    }
    __syncthreads();
    int excl = x - v + (wid ? wsum[wid - 1] : 0);
    if (gid < n) g_rowoff[gid] = excl;
    if (tid == 1023) g_bsum[blockIdx.x] = wsum[31];
}

__global__ __launch_bounds__(1024) void scan_add_kernel(int n, int nb, int E) {
    __shared__ int s[64];
    __shared__ int orig[64];
    int tid = threadIdx.x;
    if (tid < 64) {
        int v = (tid < nb) ? g_bsum[tid] : 0;
        s[tid] = v; orig[tid] = v;
    }
    __syncthreads();
    #pragma unroll
    for (int off = 1; off < 64; off <<= 1) {
        int t = (tid < 64 && tid >= off) ? s[tid - off] : 0;
        __syncthreads();
        if (tid < 64) s[tid] += t;
        __syncthreads();
    }
    int boff = s[blockIdx.x] - orig[blockIdx.x];
    int gid = blockIdx.x * 1024 + tid;
    if (gid < n) g_rowoff[gid] += boff;
    if (blockIdx.x == 0 && tid == 0) g_rowoff[n] = E;
}

// atomic-free: position = rowoff[src] + precomputed rank
__global__ void scatter_kernel(const int* __restrict__ esrc,
                               const int* __restrict__ edst, int E) {
    int e = blockIdx.x * blockDim.x + threadIdx.x;
    if (e < E) {
        int s = esrc[e];
        g_adj[g_rowoff[s] + g_rank[e]] = edst[e];
    }
}

// ------------------------------ mma helpers --------------------------------
#define LDSM4(R0,R1,R2,R3,addr) \
  asm volatile("ldmatrix.sync.aligned.m8n8.x4.shared.b16 {%0,%1,%2,%3}, [%4];" \
    : "=r"(R0),"=r"(R1),"=r"(R2),"=r"(R3) : "r"(addr))

#define MMA16816(D,A,B0,B1) \
  asm volatile("mma.sync.aligned.m16n8k16.row.col.f32.bf16.bf16.f32 " \
    "{%0,%1,%2,%3}, {%4,%5,%6,%7}, {%8,%9}, {%0,%1,%2,%3};" \
    : "+f"(D[0]),"+f"(D[1]),"+f"(D[2]),"+f"(D[3]) \
    : "r"(A[0]),"r"(A[1]),"r"(A[2]),"r"(A[3]),"r"(B0),"r"(B1))

#define CP16(dst, src, n) \
  asm volatile("cp.async.cg.shared.global [%0], [%1], 16, %2;" \
    :: "r"(dst), "l"(src), "r"(n))
#define CP_COMMIT asm volatile("cp.async.commit_group;")

__device__ __forceinline__ uint4 cvt8(float4 a, float4 b) {
    __nv_bfloat162 p0 = __floats2bfloat162_rn(a.x, a.y);
    __nv_bfloat162 p1 = __floats2bfloat162_rn(a.z, a.w);
    __nv_bfloat162 p2 = __floats2bfloat162_rn(b.x, b.y);
    __nv_bfloat162 p3 = __floats2bfloat162_rn(b.z, b.w);
    uint4 u;
    u.x = *(unsigned*)&p0; u.y = *(unsigned*)&p1;
    u.z = *(unsigned*)&p2; u.w = *(unsigned*)&p3;
    return u;
}

// ------------------------- packed f32x2 helpers ----------------------------
__device__ __forceinline__ unsigned long long packf2(float w) {
    unsigned long long r;
    asm("mov.b64 %0, {%1, %1};" : "=l"(r) : "f"(w));
    return r;
}
__device__ __forceinline__ void bf2fma(unsigned long long& acc, unsigned v,
                                       unsigned long long wp) {
    unsigned lo, hi;
    unsigned long long p;
    asm("prmt.b32 %0, %1, 0, 0x1044;" : "=r"(lo) : "r"(v));
    asm("prmt.b32 %0, %1, 0, 0x3244;" : "=r"(hi) : "r"(v));
    asm("mov.b64 %0, {%1, %2};" : "=l"(p) : "r"(lo), "r"(hi));
    asm("fma.rn.f32x2 %0, %1, %2, %0;" : "+l"(acc) : "l"(p), "l"(wp));
}

// ---------------------- GEMM1 (mma + fused attn1 + fused x cvt) ------------
__global__ __launch_bounds__(256, 2) void gemm1_mma(const float* __restrict__ x,
                                                    const float* __restrict__ b1,
                                                    const float* __restrict__ a1,
                                                    int M) {
    const int PAD = 40;
    const int BUFE = 128 * PAD;
    __shared__ __align__(16) __nv_bfloat16 As[2 * BUFE];
    __shared__ __align__(16) __nv_bfloat16 Bs[2 * BUFE];
    int bx = blockIdx.x & 3;
    int by = blockIdx.x >> 2;
    int m0 = by * 128, n0 = bx * 128;
    int tid = threadIdx.x, lane = tid & 31, wid = tid >> 5;
    int wm = (wid & 3) * 32, wn = (wid >> 2) * 64;

    float acc[2][8][4];
    #pragma unroll
    for (int i = 0; i < 2; i++)
        #pragma unroll
        for (int j = 0; j < 8; j++)
            #pragma unroll
            for (int k = 0; k < 4; k++) acc[i][j][k] = 0.f;

    int lr = lane & 7, lb8 = (lane >> 3) & 1, lhi = lane >> 4;
    uint32_t smB = (uint32_t)__cvta_generic_to_shared(Bs);
    uint32_t smA = (uint32_t)__cvta_generic_to_shared(As);
    uint32_t aBase = (uint32_t)((wm + lr + lb8 * 8) * PAD + lhi * 8) * 2;
    uint32_t bBase = (uint32_t)((wn + lr + lhi * 8) * PAD + lb8 * 8) * 2;

    int row0 = tid >> 2, q0 = tid & 3;
    int row1 = row0 + 64, q1 = q0;

    const float4 f4z = make_float4(0.f, 0.f, 0.f, 0.f);
    uint4 ua0, ua1;

    #define LDCVTA(k0) {                                                       \
        int gr0 = m0 + row0, gr1 = m0 + row1;                                  \
        const float* p0 = x + (size_t)(gr0 < M ? gr0 : 0) * NFEAT + (k0) + q0 * 8; \
        const float* p1 = x + (size_t)(gr1 < M ? gr1 : 0) * NFEAT + (k0) + q1 * 8; \
        float4 t0 = __ldg((const float4*)p0), t1 = __ldg((const float4*)p0 + 1); \
        float4 t2 = __ldg((const float4*)p1), t3 = __ldg((const float4*)p1 + 1); \
        if (gr0 >= M) { t0 = f4z; t1 = f4z; }                                  \
        if (gr1 >= M) { t2 = f4z; t3 = f4z; }                                  \
        ua0 = cvt8(t0, t1); ua1 = cvt8(t2, t3);                                \
    }
    #define STA(buf) {                                                         \
        *(uint4*)(&As[(buf) * BUFE + row0 * PAD + q0 * 8]) = ua0;              \
        *(uint4*)(&As[(buf) * BUFE + row1 * PAD + q1 * 8]) = ua1;              \
    }
    #define STAGEB(buf, k0) {                                                  \
        CP16(smB + (buf) * BUFE * 2 + (row0 * PAD + q0 * 8) * 2,               \
             g_WcatT + (size_t)(n0 + row0) * NFEAT + (k0) + q0 * 8, 16);       \
        CP16(smB + (buf) * BUFE * 2 + (row1 * PAD + q1 * 8) * 2,               \
             g_WcatT + (size_t)(n0 + row1) * NFEAT + (k0) + q1 * 8, 16);       \
    }

    LDCVTA(0);
    STAGEB(0, 0); CP_COMMIT;
    for (int kt = 0; kt < 8; kt++) {
        STA(kt & 1);
        if (kt < 7) {
            LDCVTA((kt + 1) * 32);
            STAGEB((kt + 1) & 1, (kt + 1) * 32); CP_COMMIT;
            asm volatile("cp.async.wait_group 1;");
        } else {
            asm volatile("cp.async.wait_group 0;");
        }
        __syncthreads();
        uint32_t aAddr = smA + (kt & 1) * BUFE * 2 + aBase;
        uint32_t bAddr = smB + (kt & 1) * BUFE * 2 + bBase;
        #pragma unroll
        for (int ks = 0; ks < 2; ks++) {
            uint32_t a[2][4], b[4][4];
            #pragma unroll
            for (int mt = 0; mt < 2; mt++)
                LDSM4(a[mt][0], a[mt][1], a[mt][2], a[mt][3],
                      aAddr + mt * 16 * PAD * 2 + ks * 32);
            #pragma unroll
            for (int np = 0; np < 4; np++)
                LDSM4(b[np][0], b[np][1], b[np][2], b[np][3],
                      bAddr + np * 16 * PAD * 2 + ks * 32);
            #pragma unroll
            for (int mt = 0; mt < 2; mt++)
                #pragma unroll
                for (int nt = 0; nt < 8; nt++) {
                    uint32_t b0 = b[nt >> 1][(nt & 1) * 2];
                    uint32_t b1r = b[nt >> 1][(nt & 1) * 2 + 1];
                    MMA16816(acc[mt][nt], a[mt], b0, b1r);
                }
        }
        __syncthreads();
    }

    int gid = lane >> 2, tig = lane & 3;
    int h = (n0 >> 6) + (wid >> 2);
    float ss[4] = {0.f, 0.f, 0.f, 0.f};
    float sd[4] = {0.f, 0.f, 0.f, 0.f};
    #pragma unroll
    for (int mt = 0; mt < 2; mt++) {
        #pragma unroll
        for (int nt = 0; nt < 8; nt++) {
            int j = nt * 8 + tig * 2;
            int c = n0 + wn + j;
            float bb0 = b1[c], bb1 = b1[c + 1];
            float avs0 = a1[h * 128 + j],      avs1 = a1[h * 128 + j + 1];
            float avd0 = a1[h * 128 + 64 + j], avd1 = a1[h * 128 + 64 + j + 1];
            float v0 = acc[mt][nt][0] + bb0, v1 = acc[mt][nt][1] + bb1;
            float v2 = acc[mt][nt][2] + bb0, v3 = acc[mt][nt][3] + bb1;
            ss[mt * 2 + 0] += v0 * avs0 + v1 * avs1;
            sd[mt * 2 + 0] += v0 * avd0 + v1 * avd1;
            ss[mt * 2 + 1] += v2 * avs0 + v3 * avs1;
            sd[mt * 2 + 1] += v2 * avd0 + v3 * avd1;
            int r = m0 + wm + mt * 16 + gid;
            if (r < M) {
                __nv_bfloat162 p = __floats2bfloat162_rn(v0, v1);
                *(unsigned*)(g_H1b + (size_t)r * F1 + c) = *(unsigned*)&p;
            }
            if (r + 8 < M) {
                __nv_bfloat162 p = __floats2bfloat162_rn(v2, v3);
                *(unsigned*)(g_H1b + (size_t)(r + 8) * F1 + c) = *(unsigned*)&p;
            }
        }
    }
    #pragma unroll
    for (int q = 0; q < 4; q++) {
        ss[q] += __shfl_xor_sync(0xffffffffu, ss[q], 1);
        ss[q] += __shfl_xor_sync(0xffffffffu, ss[q], 2);
        sd[q] += __shfl_xor_sync(0xffffffffu, sd[q], 1);
        sd[q] += __shfl_xor_sync(0xffffffffu, sd[q], 2);
    }
    if (tig == 0) {
        #pragma unroll
        for (int q = 0; q < 4; q++) {
            int r = m0 + wm + (q >> 1) * 16 + gid + (q & 1) * 8;
            if (r < M) {
                g_esrc[r * NHEAD + h] = make_float2(__expf(ss[q]), __expf(ALPHA * ss[q]));
                g_edst[r * NHEAD + h] = make_float2(__expf(sd[q]), __expf(ALPHA * sd[q]));
            }
        }
    }
}

// ------------------------------- agg1 --------------------------------------
#define CH1 64
__global__ __launch_bounds__(64) void agg1_kernel(int base) {
    int n = base + blockIdx.x;
    int tid = threadIdx.x;
    int head = tid >> 3;
    __shared__ int   sdst[CH1];
    __shared__ float sw[CH1 * NHEAD];
    __shared__ float2 ses[NHEAD];
    if (tid < NHEAD) ses[tid] = g_esrc[n * NHEAD + tid];
    int start = g_rowoff[n], end = g_rowoff[n + 1];
    unsigned long long accp[4] = {0ull, 0ull, 0ull, 0ull};
    float sumw = 0.f;
    __syncthreads();

    for (int e0 = start; e0 < end; e0 += CH1) {
        int ne = min(CH1, end - e0);
        if (tid < ne) sdst[tid] = g_adj[e0 + tid];
        __syncthreads();
        #pragma unroll
        for (int it = 0; it < 4; it++) {
            int idx = tid + it * 64;
            if (idx < ne * 4) {
                int i = idx >> 2, h2 = (idx & 3) * 2;
                float4 ed = __ldg((const float4*)&g_edst[sdst[i] * NHEAD + h2]);
                float2 es0 = ses[h2], es1 = ses[h2 + 1];
                float p0 = es0.x * ed.x;
                float p1 = es1.x * ed.z;
                sw[i * NHEAD + h2]     = (p0 > 1.f) ? p0 : es0.y * ed.y;
                sw[i * NHEAD + h2 + 1] = (p1 > 1.f) ? p1 : es1.y * ed.w;
            }
        }
        __syncthreads();
        int i = 0;
        for (; i + 4 <= ne; i += 4) {
            float w0 = sw[(i + 0) * NHEAD + head];
            float w1 = sw[(i + 1) * NHEAD + head];
            float w2 = sw[(i + 2) * NHEAD + head];
            float w3 = sw[(i + 3) * NHEAD + head];
            uint4 p0 = __ldg((const uint4*)(g_H1b + (size_t)sdst[i + 0] * F1 + tid * 8));
            uint4 p1 = __ldg((const uint4*)(g_H1b + (size_t)sdst[i + 1] * F1 + tid * 8));
            uint4 p2 = __ldg((const uint4*)(g_H1b + (size_t)sdst[i + 2] * F1 + tid * 8));
            uint4 p3 = __ldg((const uint4*)(g_H1b + (size_t)sdst[i + 3] * F1 + tid * 8));
            sumw += (w0 + w1) + (w2 + w3);
            unsigned long long wp0 = packf2(w0), wp1 = packf2(w1);
            unsigned long long wp2 = packf2(w2), wp3 = packf2(w3);
            bf2fma(accp[0], p0.x, wp0); bf2fma(accp[1], p0.y, wp0);
            bf2fma(accp[2], p0.z, wp0); bf2fma(accp[3], p0.w, wp0);
            bf2fma(accp[0], p1.x, wp1); bf2fma(accp[1], p1.y, wp1);
            bf2fma(accp[2], p1.z, wp1); bf2fma(accp[3], p1.w, wp1);
            bf2fma(accp[0], p2.x, wp2); bf2fma(accp[1], p2.y, wp2);
            bf2fma(accp[2], p2.z, wp2); bf2fma(accp[3], p2.w, wp2);
            bf2fma(accp[0], p3.x, wp3); bf2fma(accp[1], p3.y, wp3);
            bf2fma(accp[2], p3.z, wp3); bf2fma(accp[3], p3.w, wp3);
        }
        for (; i < ne; i++) {
            float w = sw[i * NHEAD + head];
            sumw += w;
            uint4 p = __ldg((const uint4*)(g_H1b + (size_t)sdst[i] * F1 + tid * 8));
            unsigned long long wp = packf2(w);
            bf2fma(accp[0], p.x, wp); bf2fma(accp[1], p.y, wp);
            bf2fma(accp[2], p.z, wp); bf2fma(accp[3], p.w, wp);
        }
        __syncthreads();
    }
    float inv = 1.0f / sumw;
    float acc[8];
    #pragma unroll
    for (int k = 0; k < 4; k++) {
        float lo, hi;
        asm("mov.b64 {%0, %1}, %2;" : "=f"(lo), "=f"(hi) : "l"(accp[k]));
        acc[2 * k] = lo; acc[2 * k + 1] = hi;
    }
    #pragma unroll
    for (int k = 0; k < 8; k++) {
        float v = acc[k] * inv;
        acc[k] = v > 0.f ? v : (__expf(v) - 1.f);
    }
    __nv_bfloat162 q0 = __floats2bfloat162_rn(acc[0], acc[1]);
    __nv_bfloat162 q1 = __floats2bfloat162_rn(acc[2], acc[3]);
    __nv_bfloat162 q2 = __floats2bfloat162_rn(acc[4], acc[5]);
    __nv_bfloat162 q3 = __floats2bfloat162_rn(acc[6], acc[7]);
    uint4 u;
    u.x = *(unsigned*)&q0; u.y = *(unsigned*)&q1;
    u.z = *(unsigned*)&q2; u.w = *(unsigned*)&q3;
    *(uint4*)(g_ACC1b + (size_t)n * F1 + tid * 8) = u;
}

// ---------------------- GEMM2 (mma + fused attn2) --------------------------
__global__ __launch_bounds__(256, 2) void gemm2_mma(const float* __restrict__ b2,
                                                    const float* __restrict__ a2,
                                                    int mbase, int M) {
    const int PAD = 40;
    __shared__ __align__(16) __nv_bfloat16 As[128 * PAD];
    __shared__ __align__(16) __nv_bfloat16 Bs[64 * PAD];
    int m0 = mbase + blockIdx.x * 128;
    int tid = threadIdx.x, lane = tid & 31, wid = tid >> 5;
    int wm = wid * 16;

    float acc[5][4];
    #pragma unroll
    for (int j = 0; j < 5; j++)
        #pragma unroll
        for (int k = 0; k < 4; k++) acc[j][k] = 0.f;

    int lr = lane & 7, lb8 = (lane >> 3) & 1, lhi = lane >> 4;
    uint32_t smA = (uint32_t)__cvta_generic_to_shared(As);
    uint32_t smB = (uint32_t)__cvta_generic_to_shared(Bs);
    uint32_t aAddr = smA + (uint32_t)((wm + lr + lb8 * 8) * PAD + lhi * 8) * 2;
    uint32_t bAddr = smB + (uint32_t)((lr + lhi * 8) * PAD + lb8 * 8) * 2;

    for (int k0 = 0; k0 < F1; k0 += 32) {
        #pragma unroll
        for (int it = 0; it < 2; it++) {
            int idx = tid + it * 256;
            int row = idx >> 2, q = idx & 3;
            int gr = m0 + row;
            uint4 v = make_uint4(0, 0, 0, 0);
            if (gr < M)
                v = *(const uint4*)(g_ACC1b + (size_t)gr * F1 + k0 + q * 8);
            *(uint4*)(&As[row * PAD + q * 8]) = v;
        }
        {
            int row = tid >> 2, q = tid & 3;
            uint4 w = *(const uint4*)(g_W2T + (size_t)row * F1 + k0 + q * 8);
            *(uint4*)(&Bs[row * PAD + q * 8]) = w;
        }
        __syncthreads();
        #pragma unroll
        for (int ks = 0; ks < 2; ks++) {
            uint32_t a[4], b[3][4];
            LDSM4(a[0], a[1], a[2], a[3], aAddr + ks * 32);
            #pragma unroll
            for (int np = 0; np < 3; np++)
                LDSM4(b[np][0], b[np][1], b[np][2], b[np][3],
                      bAddr + np * 16 * PAD * 2 + ks * 32);
            #pragma unroll
            for (int nt = 0; nt < 5; nt++) {
                uint32_t b0 = b[nt >> 1][(nt & 1) * 2];
                uint32_t b1r = b[nt >> 1][(nt & 1) * 2 + 1];
                MMA16816(acc[nt], a, b0, b1r);
            }
        }
        __syncthreads();
    }

    int gid = lane >> 2, tig = lane & 3;
    float ss[2] = {0.f, 0.f}, sd[2] = {0.f, 0.f};
    int r0 = m0 + wm + gid;
    #pragma unroll
    for (int nt = 0; nt < 5; nt++) {
        int c = nt * 8 + tig * 2;
        float bb0 = b2[c], bb1 = b2[c + 1];
        float as0 = a2[c], as1 = a2[c + 1];
        float ad0 = a2[NCLASS + c], ad1 = a2[NCLASS + c + 1];
        float v0 = acc[nt][0] + bb0, v1 = acc[nt][1] + bb1;
        float v2 = acc[nt][2] + bb0, v3 = acc[nt][3] + bb1;
        ss[0] += v0 * as0 + v1 * as1; sd[0] += v0 * ad0 + v1 * ad1;
        ss[1] += v2 * as0 + v3 * as1; sd[1] += v2 * ad0 + v3 * ad1;
        if (r0 < M) {
            __nv_bfloat162 p = __floats2bfloat162_rn(v0, v1);
            *(unsigned*)(g_H2b + (size_t)r0 * H2S + c) = *(unsigned*)&p;
        }
        if (r0 + 8 < M) {
            __nv_bfloat162 p = __floats2bfloat162_rn(v2, v3);
            *(unsigned*)(g_H2b + (size_t)(r0 + 8) * H2S + c) = *(unsigned*)&p;
        }
    }
    #pragma unroll
    for (int q = 0; q < 2; q++) {
        ss[q] += __shfl_xor_sync(0xffffffffu, ss[q], 1);
        ss[q] += __shfl_xor_sync(0xffffffffu, ss[q], 2);
        sd[q] += __shfl_xor_sync(0xffffffffu, sd[q], 1);
        sd[q] += __shfl_xor_sync(0xffffffffu, sd[q], 2);
    }
    if (tig == 0) {
        #pragma unroll
        for (int q = 0; q < 2; q++) {
            int r = r0 + q * 8;
            if (r < M) {
                g_e2src[r] = make_float2(__expf(ss[q]), __expf(ALPHA * ss[q]));
                g_e2dst[r] = make_float2(__expf(sd[q]), __expf(ALPHA * sd[q]));
            }
        }
    }
}

// --------------------------- agg2 + log_softmax ----------------------------
#define CH2 64
__global__ __launch_bounds__(64) void agg2_kernel(float* __restrict__ out) {
    int n = blockIdx.x;
    int tid = threadIdx.x;
    int g = tid / 20, l = tid % 20;
    __shared__ int   sdst[CH2];
    __shared__ float sw[CH2];
    __shared__ unsigned long long pacc[3][20];
    __shared__ float psum[3];
    float2 es = g_e2src[n];
    int start = g_rowoff[n], end = g_rowoff[n + 1];
    unsigned long long accp = 0ull;
    float sumw = 0.f;

    for (int e0 = start; e0 < end; e0 += CH2) {
        int ne = min(CH2, end - e0);
        if (tid < ne) {
            int d = g_adj[e0 + tid];
            sdst[tid] = d;
            float2 ed = __ldg(&g_e2dst[d]);
            float p1 = es.x * ed.x;
            sw[tid] = (p1 > 1.f) ? p1 : es.y * ed.y;
        }
        __syncthreads();
        if (g < 3) {
            int i = g;
            for (; i + 3 < ne; i += 6) {
                float w0 = sw[i], w1 = sw[i + 3];
                sumw += w0 + w1;
                unsigned v0 = *(const unsigned*)(g_H2b + (size_t)sdst[i] * H2S + 2 * l);
                unsigned v1 = *(const unsigned*)(g_H2b + (size_t)sdst[i + 3] * H2S + 2 * l);
                bf2fma(accp, v0, packf2(w0));
                bf2fma(accp, v1, packf2(w1));
            }
            if (i < ne) {
                float w = sw[i];
                sumw += w;
                unsigned v = *(const unsigned*)(g_H2b + (size_t)sdst[i] * H2S + 2 * l);
                bf2fma(accp, v, packf2(w));
            }
        }
        __syncthreads();
    }
    if (g < 3) {
        pacc[g][l] = accp;
        if (l == 0) psum[g] = sumw;
    }
    __syncthreads();

    __shared__ float red[64];
    if (tid < 20) {
        float tot = psum[0] + psum[1] + psum[2];
        float a0, a1, b0, b1, c0, c1;
        asm("mov.b64 {%0, %1}, %2;" : "=f"(a0), "=f"(a1) : "l"(pacc[0][tid]));
        asm("mov.b64 {%0, %1}, %2;" : "=f"(b0), "=f"(b1) : "l"(pacc[1][tid]));
        asm("mov.b64 {%0, %1}, %2;" : "=f"(c0), "=f"(c1) : "l"(pacc[2][tid]));
        float inv = 1.0f / tot;
        red[2 * tid]     = (a0 + b0 + c0) * inv;
        red[2 * tid + 1] = (a1 + b1 + c1) * inv;
    } else if (tid >= 40) {
        red[tid] = -1e30f;
    }
    __syncthreads();
    float v = red[tid];
    #pragma unroll
    for (int s = 32; s; s >>= 1) {
        if (tid < s) red[tid] = fmaxf(red[tid], red[tid + s]);
        __syncthreads();
    }
    float mx = red[0];
    __syncthreads();
    red[tid] = (tid < NCLASS) ? __expf(v - mx) : 0.f;
    __syncthreads();
    #pragma unroll
    for (int s = 32; s; s >>= 1) {
        if (tid < s) red[tid] += red[tid + s];
        __syncthreads();
    }
    float lse = logf(red[0]) + mx;
    if (tid < NCLASS) out[(size_t)n * NCLASS + tid] = v - lse;
}

// ------------------------------- launcher ----------------------------------
extern "C" void kernel_launch(void* const* d_in, const int* in_sizes, int n_in,
                              void* d_out, int out_size) {
    const float* x  = (const float*)d_in[0];
    const int*   ed = (const int*)  d_in[1];
    const float* W1 = (const float*)d_in[2];
    const float* b1 = (const float*)d_in[3];
    const float* a1 = (const float*)d_in[4];
    const float* W2 = (const float*)d_in[5];
    const float* b2 = (const float*)d_in[6];
    const float* a2 = (const float*)d_in[7];
    float* out = (float*)d_out;

    int N = in_sizes[0] / NFEAT;
    int E = in_sizes[1] / 2;
    const int* esrc = ed;
    const int* edst = ed + E;
    int NB = (N + 1023) / 1024;

    static cudaStream_t s1 = nullptr;
    static cudaEvent_t ev0 = nullptr, evW = nullptr, ev1 = nullptr;
    static cudaEvent_t evA = nullptr, evG = nullptr;
    static void* p_deg = nullptr;
    if (s1 == nullptr) {
        cudaStreamCreateWithFlags(&s1, cudaStreamNonBlocking);
        cudaEventCreateWithFlags(&ev0, cudaEventDisableTiming);
        cudaEventCreateWithFlags(&evW, cudaEventDisableTiming);
        cudaEventCreateWithFlags(&ev1, cudaEventDisableTiming);
        cudaEventCreateWithFlags(&evA, cudaEventDisableTiming);
        cudaEventCreateWithFlags(&evG, cudaEventDisableTiming);
        cudaGetSymbolAddress(&p_deg, g_deg);
    }

    cudaEventRecord(ev0, 0);
    cudaStreamWaitEvent(s1, ev0, 0);

    // side chain on s1 (R9 schedule)
    repack_weights<<<256, 256, 0, s1>>>(W1, W2);
    cudaEventRecord(evW, s1);
    cudaMemsetAsync(p_deg, 0, N * sizeof(int), s1);
    hist_kernel<<<(E + 255) / 256, 256, 0, s1>>>(esrc, E);
    scan_block_kernel<<<NB, 1024, 0, s1>>>(N);
    scan_add_kernel<<<NB, 1024, 0, s1>>>(N, NB, E);
    scatter_kernel<<<(E + 255) / 256, 256, 0, s1>>>(esrc, edst, E);
    cudaEventRecord(ev1, s1);

    // main: gemm1 needs only WcatT from the side chain
    cudaStreamWaitEvent(0, evW, 0);
    gemm1_mma<<<((N + 127) / 128) * (F1 / 128), 256>>>(x, b1, a1, N);

    // 2-stage agg1 / gemm2 overlap (R9 configuration)
    int NA = 25088;
    if (NA > N) NA = (N / 128) * 128;
    int nb0 = NA / 128;
    int nb1 = (N - NA + 127) / 128;

    cudaStreamWaitEvent(0, ev1, 0);
    agg1_kernel<<<NA, 64>>>(0);
    cudaEventRecord(evA, 0);
    agg1_kernel<<<N - NA, 64>>>(NA);

    cudaStreamWaitEvent(s1, evA, 0);
    gemm2_mma<<<nb0, 256, 0, s1>>>(b2, a2, 0, N);
    cudaEventRecord(evG, s1);

    gemm2_mma<<<nb1, 256>>>(b2, a2, NA, N);
    cudaStreamWaitEvent(0, evG, 0);
    agg2_kernel<<<N, 64>>>(out);
}